// round 5
// baseline (speedup 1.0000x reference)
#include <cuda_runtime.h>
#include <cuda_bf16.h>
#include <cstdint>

#define Bq 2
#define Sq 2048
#define Dq 1024
#define Hq 16
#define HDq 64
#define Mq (Bq*Sq)

// ---------------- global scratch (allocation-free) ----------------
__device__ __align__(16) __nv_bfloat16 gXh[Mq*Dq], gXl[Mq*Dq];
__device__ __align__(16) __nv_bfloat16 gWh[4][Dq*Dq], gWl[4][Dq*Dq];
__device__ __align__(16) __nv_bfloat16 gQh[Mq*Dq], gQl[Mq*Dq];
__device__ __align__(16) __nv_bfloat16 gKh[Mq*Dq], gKl[Mq*Dq];
__device__ __align__(16) __nv_bfloat16 gVh[Mq*Dq], gVl[Mq*Dq];
__device__ __align__(16) __nv_bfloat16 gCh[Mq*Dq], gCl[Mq*Dq];

// ---------------- small helpers ----------------
__device__ __forceinline__ void split2(float x, float y,
                                       uint32_t& hi, uint32_t& lo) {
    __nv_bfloat16 hx = __float2bfloat16_rn(x);
    __nv_bfloat16 hy = __float2bfloat16_rn(y);
    __nv_bfloat162 h2 = __halves2bfloat162(hx, hy);
    __nv_bfloat162 l2 = __halves2bfloat162(
        __float2bfloat16_rn(x - __bfloat162float(hx)),
        __float2bfloat16_rn(y - __bfloat162float(hy)));
    hi = *reinterpret_cast<uint32_t*>(&h2);
    lo = *reinterpret_cast<uint32_t*>(&l2);
}

__device__ __forceinline__ void mma16816(float* c, const uint32_t* a,
                                         uint32_t b0, uint32_t b1) {
    asm volatile("mma.sync.aligned.m16n8k16.row.col.f32.bf16.bf16.f32 "
                 "{%0,%1,%2,%3}, {%4,%5,%6,%7}, {%8,%9}, {%0,%1,%2,%3};"
                 : "+f"(c[0]), "+f"(c[1]), "+f"(c[2]), "+f"(c[3])
                 : "r"(a[0]), "r"(a[1]), "r"(a[2]), "r"(a[3]),
                   "r"(b0), "r"(b1));
}

__device__ __forceinline__ void ldm_x4(uint32_t* r, uint32_t a) {
    asm volatile("ldmatrix.sync.aligned.m8n8.x4.shared.b16 {%0,%1,%2,%3}, [%4];"
                 : "=r"(r[0]), "=r"(r[1]), "=r"(r[2]), "=r"(r[3]) : "r"(a));
}
__device__ __forceinline__ void ldm_x4_t(uint32_t* r, uint32_t a) {
    asm volatile("ldmatrix.sync.aligned.m8n8.x4.trans.shared.b16 {%0,%1,%2,%3}, [%4];"
                 : "=r"(r[0]), "=r"(r[1]), "=r"(r[2]), "=r"(r[3]) : "r"(a));
}

__device__ __forceinline__ uint32_t smem_u32(const void* p) {
    uint32_t a;
    asm("{ .reg .u64 t; cvta.to.shared.u64 t, %1; cvt.u32.u64 %0, t; }"
        : "=r"(a) : "l"(p));
    return a;
}

__device__ __forceinline__ void cp16(uint32_t dst, const void* src) {
    asm volatile("cp.async.cg.shared.global [%0], [%1], 16;" :: "r"(dst), "l"(src));
}
__device__ __forceinline__ void cp_commit() {
    asm volatile("cp.async.commit_group;" ::: "memory");
}

// ---------------------------------------------------------------------------
// split kernels: f32 -> bf16 hi/lo
// ---------------------------------------------------------------------------
__global__ void split_kernel(const float* __restrict__ src,
                             __nv_bfloat16* __restrict__ hi,
                             __nv_bfloat16* __restrict__ lo,
                             int n4, float scale)
{
    int i = blockIdx.x * blockDim.x + threadIdx.x;
    if (i >= n4) return;
    float4 v = ((const float4*)src)[i];
    uint32_t h0, l0, h1, l1;
    split2(v.x * scale, v.y * scale, h0, l0);
    split2(v.z * scale, v.w * scale, h1, l1);
    ((uint2*)hi)[i] = make_uint2(h0, h1);
    ((uint2*)lo)[i] = make_uint2(l0, l1);
}

// fused 4-weight split: grid.y selects matrix; Wq (y==0) gets 1/8 scale
__global__ void split4_kernel(const float* __restrict__ w0,
                              const float* __restrict__ w1,
                              const float* __restrict__ w2,
                              const float* __restrict__ w3,
                              __nv_bfloat16* __restrict__ hi,
                              __nv_bfloat16* __restrict__ lo, int n4)
{
    int i = blockIdx.x * blockDim.x + threadIdx.x;
    if (i >= n4) return;
    int y = blockIdx.y;
    const float* src = (y == 0) ? w0 : (y == 1) ? w1 : (y == 2) ? w2 : w3;
    float scale = (y == 0) ? 0.125f : 1.0f;
    float4 v = ((const float4*)src)[i];
    uint32_t h0, l0, h1, l1;
    split2(v.x * scale, v.y * scale, h0, l0);
    split2(v.z * scale, v.w * scale, h1, l1);
    size_t o = (size_t)y * (Dq * (size_t)Dq / 4) + i;
    ((uint2*)hi)[o] = make_uint2(h0, h1);
    ((uint2*)lo)[o] = make_uint2(l0, l1);
}

// ---------------------------------------------------------------------------
// bf16x3 GEMM, mma.sync + ldmatrix + 3-stage cp.async pipeline.
// O[m,n] = sum_k (Ah+Al)[m,k]*(Bh+Bl)[n,k] + bias[n]*bscale
// 128x128 CTA tile, BK=32, 256 thr, warp tile 64x32 (2x4 warp grid).
// smem rows: 32 bf16 = 64B data, stride 80B (conflict-free).
// ---------------------------------------------------------------------------
#define GST 80
#define ATB (128*GST)          // 10240 bytes per array tile
#define STAGE_B (4*ATB)        // Ah,Al,Bh,Bl = 40960
#define GEMM_SMEM (3*STAGE_B)  // 122880

__global__ void __launch_bounds__(256) gemm_tc(
    const __nv_bfloat16* __restrict__ Ah, const __nv_bfloat16* __restrict__ Al,
    const __nv_bfloat16* __restrict__ Bh, const __nv_bfloat16* __restrict__ Bl,
    const float* __restrict__ bias, float bscale,
    float* __restrict__ outF,
    __nv_bfloat16* __restrict__ outH, __nv_bfloat16* __restrict__ outL,
    int writeF)
{
    extern __shared__ char smem[];
    const uint32_t sb = smem_u32(smem);
    const int tid = threadIdx.x;
    const int wid = tid >> 5, lane = tid & 31;
    const int g = lane >> 2, tig = lane & 3;
    const int q4 = lane >> 3, m8 = lane & 7;
    const int wm = wid & 1, wn = wid >> 1;
    const int m0 = blockIdx.y * 128, n0 = blockIdx.x * 128;

    // loader role: each 64-thread group owns one array
    const int grp = tid >> 6, tg = tid & 63;
    const __nv_bfloat16* msrc =
        (grp == 0) ? Ah + (size_t)m0 * Dq :
        (grp == 1) ? Al + (size_t)m0 * Dq :
        (grp == 2) ? Bh + (size_t)n0 * Dq : Bl + (size_t)n0 * Dq;
    const uint32_t aoff = grp * ATB;

    // per-lane ldmatrix bases (relative to stage base)
    const uint32_t aRel = (uint32_t)((wm*64 + ((q4&1)<<3) + m8) * GST + ((q4>>1)<<4));
    const uint32_t bRel = (uint32_t)(2*ATB + (wn*32 + ((q4>>1)<<3) + m8) * GST + ((q4&1)<<4));

    float acc[4][4][4];
#pragma unroll
    for (int i = 0; i < 4; i++)
#pragma unroll
        for (int j = 0; j < 4; j++)
#pragma unroll
            for (int r = 0; r < 4; r++) acc[i][j][r] = 0.f;

    // prefetch stages 0 and 1
#pragma unroll
    for (int p = 0; p < 2; p++) {
        const uint32_t stage = sb + p * STAGE_B;
        const int k0 = p * 32;
#pragma unroll
        for (int i = 0; i < 8; i++) {
            int chunk = tg + 64 * i;
            int r = chunk >> 2, c = chunk & 3;
            cp16(stage + aoff + r * GST + c * 16, msrc + (size_t)r * Dq + k0 + c * 8);
        }
        cp_commit();
    }

    for (int it = 0; it < 32; it++) {
        if (it < 30) asm volatile("cp.async.wait_group 1;" ::: "memory");
        else         asm volatile("cp.async.wait_group 0;" ::: "memory");
        __syncthreads();

        if (it < 30) {
            const uint32_t nstage = sb + ((it + 2) % 3) * STAGE_B;
            const int k0 = (it + 2) * 32;
#pragma unroll
            for (int i = 0; i < 8; i++) {
                int chunk = tg + 64 * i;
                int r = chunk >> 2, c = chunk & 3;
                cp16(nstage + aoff + r * GST + c * 16,
                     msrc + (size_t)r * Dq + k0 + c * 8);
            }
            cp_commit();
        }

        const uint32_t stage = sb + (it % 3) * STAGE_B;
#pragma unroll
        for (int ks = 0; ks < 2; ks++) {
            uint32_t ah[4][4], al[4][4];
#pragma unroll
            for (int i = 0; i < 4; i++) {
                ldm_x4(ah[i], stage + aRel + i * (16*GST) + ks * 32);
                ldm_x4(al[i], stage + ATB + aRel + i * (16*GST) + ks * 32);
            }
#pragma unroll
            for (int jb = 0; jb < 2; jb++) {
                uint32_t bH[4], bL[4];
                ldm_x4(bH, stage + bRel + jb * (16*GST) + ks * 32);
                ldm_x4(bL, stage + ATB + bRel + jb * (16*GST) + ks * 32);
#pragma unroll
                for (int i = 0; i < 4; i++) {
                    mma16816(acc[i][2*jb],   ah[i], bH[0], bH[1]);
                    mma16816(acc[i][2*jb],   ah[i], bL[0], bL[1]);
                    mma16816(acc[i][2*jb],   al[i], bH[0], bH[1]);
                    mma16816(acc[i][2*jb+1], ah[i], bH[2], bH[3]);
                    mma16816(acc[i][2*jb+1], ah[i], bL[2], bL[3]);
                    mma16816(acc[i][2*jb+1], al[i], bH[2], bH[3]);
                }
            }
        }
    }

    // epilogue
#pragma unroll
    for (int j = 0; j < 4; j++) {
        int cc = n0 + wn*32 + 8*j + 2*tig;
        float b0 = bias[cc] * bscale, b1 = bias[cc + 1] * bscale;
#pragma unroll
        for (int i = 0; i < 4; i++) {
            int rr = m0 + wm*64 + 16*i + g;
            float v00 = acc[i][j][0] + b0, v01 = acc[i][j][1] + b1;
            float v10 = acc[i][j][2] + b0, v11 = acc[i][j][3] + b1;
            if (writeF) {
                *(float2*)(outF + (size_t)rr * Dq + cc) = make_float2(v00, v01);
                *(float2*)(outF + (size_t)(rr + 8) * Dq + cc) = make_float2(v10, v11);
            } else {
                uint32_t h0, l0, h1, l1;
                split2(v00, v01, h0, l0);
                split2(v10, v11, h1, l1);
                size_t i0 = ((size_t)rr * Dq + cc) >> 1;
                size_t i1 = ((size_t)(rr + 8) * Dq + cc) >> 1;
                ((uint32_t*)outH)[i0] = h0; ((uint32_t*)outL)[i0] = l0;
                ((uint32_t*)outH)[i1] = h1; ((uint32_t*)outL)[i1] = l1;
            }
        }
    }
}

// ---------------------------------------------------------------------------
// Flash attention, bf16x3 mma.sync + ldmatrix, cp.async-pipelined KV.
// 128 q-rows/CTA (8 warps x 16), 64-key tiles.
// K double-buffered (load hidden behind softmax+PV), V single-buffered
// (load hidden behind QK+softmax). Mask in registers (LDG at tile top).
// smem rows 144B stride (conflict-free ldmatrix). Outputs ctx bf16 hi/lo.
// ---------------------------------------------------------------------------
#define ATT_QH 0
#define ATT_QL 18432
#define ATT_K0 36864          // K slot s: hi at +s*18432, lo at +s*18432+9216
#define ATT_V  73728          // hi +0, lo +9216
#define ATT_SMEM 92160

__global__ void __launch_bounds__(256, 2) attn_kernel(
    const __nv_bfloat16* __restrict__ Qh, const __nv_bfloat16* __restrict__ Ql,
    const __nv_bfloat16* __restrict__ Kh, const __nv_bfloat16* __restrict__ Kl,
    const __nv_bfloat16* __restrict__ Vh, const __nv_bfloat16* __restrict__ Vl,
    const float* __restrict__ mask,
    __nv_bfloat16* __restrict__ Ch, __nv_bfloat16* __restrict__ Cl)
{
    extern __shared__ char smem[];
    const uint32_t sbB = smem_u32(smem);

    const int tid = threadIdx.x;
    const int lane = tid & 31;
    const int wid = tid >> 5;
    const int g = lane >> 2, tig = lane & 3;
    const int bh = blockIdx.y;
    const int b = bh >> 4, h = bh & 15;
    const int q0 = blockIdx.x * 128;

    const size_t baseQ  = ((size_t)(b * Sq + q0)) * Dq + h * HDq;
    const size_t baseKV = ((size_t)(b * Sq)) * Dq + h * HDq;

    // per-lane ldmatrix address bases
    const int q4 = lane >> 3, m8 = lane & 7;
    const uint32_t aHb = sbB + ATT_QH + (16*wid + ((q4&1)<<3) + m8)*144 + ((q4>>1)<<4);
    const uint32_t aLb = aHb + (ATT_QL - ATT_QH);
    const uint32_t kRel = (((q4>>1)<<3) + m8)*144 + ((q4&1)<<4);
    const uint32_t vHb = sbB + ATT_V + (((q4&1)<<3) + m8)*144 + ((q4>>1)<<4);
    const uint32_t vLb = vHb + 9216;

    // KV loader role: hg 0 -> hi array, 1 -> lo array (128 threads each)
    const int hg = tid >> 7, ht = tid & 127;
    const __nv_bfloat16* ksrc = hg ? Kl : Kh;
    const __nv_bfloat16* vsrc = hg ? Vl : Vh;
    const uint32_t hoff = hg * 9216;

    // ---- load Q tile (hi/lo), natural rows (synchronous; one-time) ----
    {
        const __nv_bfloat16* src = hg ? Ql : Qh;
        const uint32_t off = hg ? ATT_QL : ATT_QH;
#pragma unroll
        for (int i = 0; i < 8; i++) {
            int chunk = ht + 128 * i;
            int r = chunk >> 3, c = chunk & 7;
            uint4 v = ((const uint4*)(src + baseQ + (size_t)r * Dq))[c];
            *(uint4*)(smem + off + r * 144 + c * 16) = v;
        }
    }

    // preload K tile 0
#pragma unroll
    for (int i = 0; i < 4; i++) {
        int chunk = ht + 128 * i;
        int r = chunk >> 3, c = chunk & 7;
        cp16(sbB + ATT_K0 + hoff + r * 144 + c * 16,
             ksrc + baseKV + (size_t)r * Dq + c * 8);
    }
    cp_commit();

    float m0r = -1e30f, m1r = -1e30f, l0 = 0.f, l1 = 0.f;
    float o[8][4];
#pragma unroll
    for (int jj = 0; jj < 8; jj++)
#pragma unroll
        for (int r = 0; r < 4; r++) o[jj][r] = 0.f;

    for (int t = 0; t < 32; t++) {
        const int k0 = t * 64;
        asm volatile("cp.async.wait_group 0;" ::: "memory");  // K(t) landed
        __syncthreads();                                      // + PV(t-1) done

        // issue V(t) into single buffer (completes behind QK+softmax)
#pragma unroll
        for (int i = 0; i < 4; i++) {
            int chunk = ht + 128 * i;
            int r = chunk >> 3, c = chunk & 7;
            cp16(sbB + ATT_V + hoff + r * 144 + c * 16,
                 vsrc + baseKV + (size_t)(k0 + r) * Dq + c * 8);
        }
        cp_commit();

        // mask values into registers (hidden behind QK)
        float2 mreg[8];
        {
            const float2* mp = (const float2*)(mask + b * Sq + k0);
#pragma unroll
            for (int j = 0; j < 8; j++) mreg[j] = mp[4*j + tig];
        }

        // ---- S = Q K^T ----
        const uint32_t kHb = sbB + ATT_K0 + (t & 1) * 18432 + kRel;
        const uint32_t kLb = kHb + 9216;
        float s[8][4];
#pragma unroll
        for (int j = 0; j < 8; j++)
#pragma unroll
            for (int r = 0; r < 4; r++) s[j][r] = 0.f;

#pragma unroll
        for (int kb = 0; kb < 4; kb++) {
            uint32_t aH[4], aL[4];
            ldm_x4(aH, aHb + kb * 32);
            ldm_x4(aL, aLb + kb * 32);
#pragma unroll
            for (int jp = 0; jp < 4; jp++) {
                uint32_t bH[4], bL[4];
                ldm_x4(bH, kHb + jp * 2304 + kb * 32);
                ldm_x4(bL, kLb + jp * 2304 + kb * 32);
                mma16816(s[2*jp],   aH, bH[0], bH[1]);
                mma16816(s[2*jp],   aH, bL[0], bL[1]);
                mma16816(s[2*jp],   aL, bH[0], bH[1]);
                mma16816(s[2*jp+1], aH, bH[2], bH[3]);
                mma16816(s[2*jp+1], aH, bL[2], bL[3]);
                mma16816(s[2*jp+1], aL, bH[2], bH[3]);
            }
        }

        // issue K(t+1) into other slot (completes behind softmax+PV)
        if (t < 31) {
            const uint32_t kdst = sbB + ATT_K0 + ((t + 1) & 1) * 18432 + hoff;
#pragma unroll
            for (int i = 0; i < 4; i++) {
                int chunk = ht + 128 * i;
                int r = chunk >> 3, c = chunk & 7;
                cp16(kdst + r * 144 + c * 16,
                     ksrc + baseKV + (size_t)(k0 + 64 + r) * Dq + c * 8);
            }
            cp_commit();
        }

        // ---- mask + online softmax ----
        float mx0 = -1e30f, mx1 = -1e30f;
#pragma unroll
        for (int j = 0; j < 8; j++) {
            s[j][0] += mreg[j].x; s[j][1] += mreg[j].y;
            s[j][2] += mreg[j].x; s[j][3] += mreg[j].y;
            mx0 = fmaxf(mx0, fmaxf(s[j][0], s[j][1]));
            mx1 = fmaxf(mx1, fmaxf(s[j][2], s[j][3]));
        }
        mx0 = fmaxf(mx0, __shfl_xor_sync(0xffffffffu, mx0, 1));
        mx0 = fmaxf(mx0, __shfl_xor_sync(0xffffffffu, mx0, 2));
        mx1 = fmaxf(mx1, __shfl_xor_sync(0xffffffffu, mx1, 1));
        mx1 = fmaxf(mx1, __shfl_xor_sync(0xffffffffu, mx1, 2));
        float mn0 = fmaxf(m0r, mx0), mn1 = fmaxf(m1r, mx1);
        float al0 = __expf(m0r - mn0), al1 = __expf(m1r - mn1);
        m0r = mn0; m1r = mn1;
        float sum0 = 0.f, sum1 = 0.f;
#pragma unroll
        for (int j = 0; j < 8; j++) {
            s[j][0] = __expf(s[j][0] - mn0); sum0 += s[j][0];
            s[j][1] = __expf(s[j][1] - mn0); sum0 += s[j][1];
            s[j][2] = __expf(s[j][2] - mn1); sum1 += s[j][2];
            s[j][3] = __expf(s[j][3] - mn1); sum1 += s[j][3];
        }
        sum0 += __shfl_xor_sync(0xffffffffu, sum0, 1);
        sum0 += __shfl_xor_sync(0xffffffffu, sum0, 2);
        sum1 += __shfl_xor_sync(0xffffffffu, sum1, 1);
        sum1 += __shfl_xor_sync(0xffffffffu, sum1, 2);
        l0 = l0 * al0 + sum0;
        l1 = l1 * al1 + sum1;
#pragma unroll
        for (int jj = 0; jj < 8; jj++) {
            o[jj][0] *= al0; o[jj][1] *= al0;
            o[jj][2] *= al1; o[jj][3] *= al1;
        }

        // ---- pack P as PV A-fragments (hi/lo) ----
        uint32_t ph[4][4], pl[4][4];
#pragma unroll
        for (int kb = 0; kb < 4; kb++) {
            split2(s[2*kb][0],   s[2*kb][1],   ph[kb][0], pl[kb][0]);
            split2(s[2*kb][2],   s[2*kb][3],   ph[kb][1], pl[kb][1]);
            split2(s[2*kb+1][0], s[2*kb+1][1], ph[kb][2], pl[kb][2]);
            split2(s[2*kb+1][2], s[2*kb+1][3], ph[kb][3], pl[kb][3]);
        }

        // V(t) done (K(t+1) may still be in flight)
        if (t < 31) asm volatile("cp.async.wait_group 1;" ::: "memory");
        else        asm volatile("cp.async.wait_group 0;" ::: "memory");
        __syncthreads();

        // ---- O += P V  (V fragments via ldmatrix.trans) ----
#pragma unroll
        for (int kb = 0; kb < 4; kb++) {
#pragma unroll
            for (int jp = 0; jp < 4; jp++) {
                uint32_t vH[4], vL[4];
                ldm_x4_t(vH, vHb + kb * 2304 + jp * 32);
                ldm_x4_t(vL, vLb + kb * 2304 + jp * 32);
                mma16816(o[2*jp],   ph[kb], vH[0], vH[1]);
                mma16816(o[2*jp],   ph[kb], vL[0], vL[1]);
                mma16816(o[2*jp],   pl[kb], vH[0], vH[1]);
                mma16816(o[2*jp+1], ph[kb], vH[2], vH[3]);
                mma16816(o[2*jp+1], ph[kb], vL[2], vL[3]);
                mma16816(o[2*jp+1], pl[kb], vH[2], vH[3]);
            }
        }
    }

    // ---- epilogue: ctx as bf16 hi/lo ----
    float inv0 = 1.0f / l0, inv1 = 1.0f / l1;
    size_t row0 = (size_t)(b * Sq + q0 + 16*wid + g);
#pragma unroll
    for (int jj = 0; jj < 8; jj++) {
        int cc = 8*jj + 2*tig;
        uint32_t h0, l0b, h1, l1b;
        split2(o[jj][0] * inv0, o[jj][1] * inv0, h0, l0b);
        split2(o[jj][2] * inv1, o[jj][3] * inv1, h1, l1b);
        size_t i0 = (row0 * Dq + h * HDq + cc) >> 1;
        size_t i1 = ((row0 + 8) * Dq + h * HDq + cc) >> 1;
        ((uint32_t*)Ch)[i0] = h0; ((uint32_t*)Cl)[i0] = l0b;
        ((uint32_t*)Ch)[i1] = h1; ((uint32_t*)Cl)[i1] = l1b;
    }
}

// ---------------------------------------------------------------------------

extern "C" void kernel_launch(void* const* d_in, const int* in_sizes, int n_in,
                              void* d_out, int out_size)
{
    const float* hs   = (const float*)d_in[0];
    const float* mask = (const float*)d_in[1];
    const float* Wq   = (const float*)d_in[2];
    const float* bq   = (const float*)d_in[3];
    const float* Wk   = (const float*)d_in[4];
    const float* bk   = (const float*)d_in[5];
    const float* Wv   = (const float*)d_in[6];
    const float* bv   = (const float*)d_in[7];
    const float* Wo   = (const float*)d_in[8];
    const float* bo   = (const float*)d_in[9];
    float* out = (float*)d_out;

    __nv_bfloat16 *xh, *xl, *wh, *wl, *qh, *ql, *kh, *kl, *vh, *vl, *ch, *cl;
    cudaGetSymbolAddress((void**)&xh, gXh); cudaGetSymbolAddress((void**)&xl, gXl);
    cudaGetSymbolAddress((void**)&wh, gWh); cudaGetSymbolAddress((void**)&wl, gWl);
    cudaGetSymbolAddress((void**)&qh, gQh); cudaGetSymbolAddress((void**)&ql, gQl);
    cudaGetSymbolAddress((void**)&kh, gKh); cudaGetSymbolAddress((void**)&kl, gKl);
    cudaGetSymbolAddress((void**)&vh, gVh); cudaGetSymbolAddress((void**)&vl, gVl);
    cudaGetSymbolAddress((void**)&ch, gCh); cudaGetSymbolAddress((void**)&cl, gCl);

    const int WN = Dq * Dq;   // elems per weight matrix

    split_kernel<<<(Mq*Dq/4 + 255)/256, 256>>>(hs, xh, xl, Mq*Dq/4, 1.0f);
    dim3 sgrid((WN/4 + 255)/256, 4);
    split4_kernel<<<sgrid, 256>>>(Wq, Wk, Wv, Wo, wh, wl, WN/4);

    cudaFuncSetAttribute(gemm_tc, cudaFuncAttributeMaxDynamicSharedMemorySize, GEMM_SMEM);
    dim3 ggrid(Dq / 128, Mq / 128);

    gemm_tc<<<ggrid, 256, GEMM_SMEM>>>(xh, xl, wh + 0*WN, wl + 0*WN, bq, 0.125f,
                                       nullptr, qh, ql, 0);
    gemm_tc<<<ggrid, 256, GEMM_SMEM>>>(xh, xl, wh + 1*WN, wl + 1*WN, bk, 1.0f,
                                       nullptr, kh, kl, 0);
    gemm_tc<<<ggrid, 256, GEMM_SMEM>>>(xh, xl, wh + 2*WN, wl + 2*WN, bv, 1.0f,
                                       nullptr, vh, vl, 0);

    cudaFuncSetAttribute(attn_kernel, cudaFuncAttributeMaxDynamicSharedMemorySize, ATT_SMEM);
    dim3 agrid(Sq / 128, Bq * Hq);
    attn_kernel<<<agrid, 256, ATT_SMEM>>>(qh, ql, kh, kl, vh, vl, mask, ch, cl);

    gemm_tc<<<ggrid, 256, GEMM_SMEM>>>(ch, cl, wh + 3*WN, wl + 3*WN, bo, 1.0f,
                                       out, nullptr, nullptr, 1);
}